// round 11
// baseline (speedup 1.0000x reference)
#include <cuda_runtime.h>
#include <math.h>

#define BSZ   32
#define AA    8400
#define GG    64
#define NCLS  80
#define TOPK  10
#define EPSV  1e-9f
#define BIGV  100000.0f

// ---------------- scratch (static device memory; no runtime alloc) ----------------
__device__ float              g_delta[(size_t)BSZ * NCLS * AA];  // [b, c, a] = log1p(-p) - log(p)
__device__ float              g_S[BSZ * AA];                     // S[b,a] = -sum_c log1p(-p)
__device__ float              g_atanP[BSZ * AA];                 // atan(w1/h1) (raw)
__device__ int                g_cnt[BSZ * AA];                   // pt_mask count per (b,a)
__device__ unsigned long long g_pick[BSZ * AA];                  // argmin key per (b,a)
__device__ int                g_topidx[BSZ * GG * TOPK];
__device__ float              g_topcost[BSZ * GG * TOPK];

// order-preserving float->uint map (monotone increasing)
__device__ __forceinline__ unsigned encf(float f) {
    unsigned u = __float_as_uint(f);
    unsigned mask = ((unsigned)((int)u >> 31)) | 0x80000000u;
    return u ^ mask;
}
__device__ __forceinline__ float decf(unsigned e) {
    unsigned u = (e & 0x80000000u) ? (e ^ 0x80000000u) : ~e;
    return __uint_as_float(u);
}

// ---------------- K0: init scratch ----------------
__global__ void k0_init() {
    int i = blockIdx.x * blockDim.x + threadIdx.x;
    if (i < BSZ * AA) { g_cnt[i] = 0; g_pick[i] = ~0ull; }
}

// ---------------- K1: prep with smem transpose. Block = 256 thr, 32 anchors.
// Identical FP ops & identical S reduction order as the validated R9 kernel:
//   lane l accumulates c = l, l+32, l+64 in order, then shfl_down 16/8/4/2/1.
// Memory is restructured only: coalesced score reads, coalesced g_delta writes.
__global__ void __launch_bounds__(256) k1_prep(const float* __restrict__ scores,
                                               const float* __restrict__ pboxes) {
    __shared__ float sm_l1[32][NCLS + 1];   // log1p(-p)
    __shared__ float sm_dl[32][NCLS + 1];   // log1p(-p) - log(p)

    int tid  = threadIdx.x;
    int lane = tid & 31, wid = tid >> 5;
    int b  = blockIdx.y;
    int a0 = blockIdx.x * 32;

    // atanP: warp 0 handles the 32 anchors (coalesced float4 loads)
    if (tid < 32) {
        int a = a0 + tid;
        if (a < AA) {
            float4 bx = reinterpret_cast<const float4*>(pboxes)[(size_t)b * AA + a];
            float w1 = __fsub_rn(bx.z, bx.x);
            float h1 = __fadd_rn(__fsub_rn(bx.w, bx.y), EPSV);
            g_atanP[b * AA + a] = atanf(__fdiv_rn(w1, h1));
        }
    }

    // Phase 1: coalesced read of 32x80 scores; compute l1 / delta into smem
    const float* sbase = scores + ((size_t)b * AA + a0) * NCLS;
    int maxE = (AA - a0 < 32 ? AA - a0 : 32) * NCLS;
#pragma unroll
    for (int e = tid; e < 32 * NCLS; e += 256) {
        if (e < maxE) {
            int ai = e / NCLS, c = e - ai * NCLS;
            float p  = fminf(fmaxf(sbase[e], 1e-7f), 0.99999994f);
            float lp = logf(p);
            float l1 = log1pf(-p);
            sm_l1[ai][c] = l1;
            sm_dl[ai][c] = __fsub_rn(l1, lp);
        }
    }
    __syncthreads();

    // Phase 2: per-anchor S reduction, exact same order as validated kernel.
    // Warp w handles anchors i = 4w..4w+3.
#pragma unroll
    for (int q = 0; q < 4; q++) {
        int i = wid * 4 + q;
        int a = a0 + i;
        float acc = 0.0f;
        acc = __fadd_rn(acc, sm_l1[i][lane]);
        acc = __fadd_rn(acc, sm_l1[i][lane + 32]);
        if (lane + 64 < NCLS) acc = __fadd_rn(acc, sm_l1[i][lane + 64]);
#pragma unroll
        for (int off = 16; off > 0; off >>= 1)
            acc = __fadd_rn(acc, __shfl_down_sync(0xffffffffu, acc, off));
        if (lane == 0 && a < AA) g_S[b * AA + a] = -acc;
    }

    // Phase 3: coalesced delta writes. Warp w writes class rows c = w, w+8, ...
    // smem read sm_dl[lane][c]: stride 81 floats -> gcd(81,32)=1, conflict-free.
    int a = a0 + lane;
    if (a < AA) {
#pragma unroll
        for (int c = wid; c < NCLS; c += 8)
            g_delta[((size_t)b * NCLS + c) * AA + a] = sm_dl[lane][c];
    }
}

// ---------------- K2: cost matrix (bit-faithful f32 emulation of reference) ----------------
__global__ void k2_cost(const float* __restrict__ pboxes, const float* __restrict__ gboxes,
                        const int* __restrict__ glabels, float* __restrict__ costOut) {
    __shared__ float sgx1[GG], sgy1[GG], sgx2[GG], sgy2[GG];
    __shared__ float sglx[GG], sgly[GG], sghx[GG], sghy[GG];
    __shared__ float sgsx[GG], sgsy[GG], swh[GG], sat[GG];
    __shared__ int   slab[GG];

    int b   = blockIdx.y;
    int tid = threadIdx.x;
    if (tid < GG) {
        float4 gb = reinterpret_cast<const float4*>(gboxes)[b * GG + tid];
        sgx1[tid] = gb.x; sgy1[tid] = gb.y; sgx2[tid] = gb.z; sgy2[tid] = gb.w;
        float gcx = __fmul_rn(__fadd_rn(gb.x, gb.z), 0.5f);
        float gcy = __fmul_rn(__fadd_rn(gb.y, gb.w), 0.5f);
        sglx[tid] = __fsub_rn(gcx, 2.5f); sghx[tid] = __fadd_rn(gcx, 2.5f);
        sgly[tid] = __fsub_rn(gcy, 2.5f); sghy[tid] = __fadd_rn(gcy, 2.5f);
        sgsx[tid] = __fadd_rn(gb.x, gb.z); sgsy[tid] = __fadd_rn(gb.y, gb.w);
        float w2 = __fsub_rn(gb.z, gb.x);
        float h2 = __fadd_rn(__fsub_rn(gb.w, gb.y), EPSV);
        swh[tid] = __fmul_rn(w2, h2);
        sat[tid] = atanf(__fdiv_rn(w2, h2));
        slab[tid] = glabels[b * GG + tid];
    }
    __syncthreads();

    int a = blockIdx.x * blockDim.x + tid;
    if (a >= AA) return;

    float4 pb = reinterpret_cast<const float4*>(pboxes)[(size_t)b * AA + a];
    float px1 = pb.x, py1 = pb.y, px2 = pb.z, py2 = pb.w;
    float w1   = __fsub_rn(px2, px1);
    float h1   = __fadd_rn(__fsub_rn(py2, py1), EPSV);
    float w1h1 = __fmul_rn(w1, h1);
    float pcx  = __fmul_rn(__fadd_rn(px1, px2), 0.5f);
    float pcy  = __fmul_rn(__fadd_rn(py1, py2), 0.5f);
    float atP  = g_atanP[b * AA + a];
    float Sv   = g_S[b * AA + a];
    const float* dbase = g_delta + (size_t)b * NCLS * AA + a;
    float* outp = costOut + (size_t)b * GG * AA + a;

#pragma unroll 8
    for (int g = 0; g < GG; g++) {
        float gx1 = sgx1[g], gy1 = sgy1[g], gx2 = sgx2[g], gy2 = sgy2[g];
        float iw    = fmaxf(__fsub_rn(fminf(px2, gx2), fmaxf(px1, gx1)), 0.0f);
        float ih    = fmaxf(__fsub_rn(fminf(py2, gy2), fmaxf(py1, gy1)), 0.0f);
        float inter = __fmul_rn(iw, ih);
        float uni   = __fadd_rn(__fsub_rn(__fadd_rn(w1h1, swh[g]), inter), EPSV);
        float iou   = __fdiv_rn(inter, uni);
        float cw = __fsub_rn(fmaxf(px2, gx2), fminf(px1, gx1));
        float ch = __fsub_rn(fmaxf(py2, gy2), fminf(py1, gy1));
        float c2 = __fadd_rn(__fadd_rn(__fmul_rn(cw, cw), __fmul_rn(ch, ch)), EPSV);
        float dx = __fsub_rn(__fsub_rn(sgsx[g], px1), px2);
        float dy = __fsub_rn(__fsub_rn(sgsy[g], py1), py2);
        float d2 = __fmul_rn(__fadd_rn(__fmul_rn(dx, dx), __fmul_rn(dy, dy)), 0.25f);
        float t = __fsub_rn(sat[g], atP);
        float v = __fmul_rn(0.4052847345693511f, __fmul_rn(t, t));
        float alpha = __fdiv_rn(v, __fadd_rn(__fsub_rn(v, iou), 1.0f));
        float ciou  = __fsub_rn(iou, __fadd_rn(__fdiv_rn(d2, c2), __fmul_rn(v, alpha)));
        float dl  = __ldg(dbase + (size_t)slab[g] * AA);
        float cls = __fadd_rn(Sv, dl);
        bool both = (pcx > gx1) & (pcy > gy1) & (gx2 > pcx) & (gy2 > pcy) &
                    (pcx > sglx[g]) & (pcy > sgly[g]) & (sghx[g] > pcx) & (sghy[g] > pcy);
        float cost = __fadd_rn(__fadd_rn(cls, __fmul_rn(3.0f, ciou)), both ? 0.0f : BIGV);
        outp[(size_t)g * AA] = cost;
    }
}

// ---------------- K3: top-10 smallest per (b,g) row. float4 stream, low regs. ----------------
__global__ void __launch_bounds__(256, 6) k3_topk(const float* __restrict__ costOut) {
    int bg = blockIdx.x;  // b*GG + g
    const float4* r4 = reinterpret_cast<const float4*>(costOut + (size_t)bg * AA);
    int tid = threadIdx.x;
    int lane = tid & 31, wid = tid >> 5;

    unsigned long long arr[TOPK];
#pragma unroll
    for (int i = 0; i < TOPK; i++) arr[i] = ~0ull;
    unsigned long long guard = ~0ull;

    // 8400 floats = 2100 float4 = 8*256 + 52
#pragma unroll
    for (int it = 0; it < 8; it++) {
        int i = tid + it * 256;
        float4 v = r4[i];
        float vv[4] = {v.x, v.y, v.z, v.w};
#pragma unroll
        for (int j = 0; j < 4; j++) {
            unsigned long long k = ((unsigned long long)encf(vv[j]) << 32) | (unsigned)(4 * i + j);
            if (k < guard) {
                arr[TOPK - 1] = k;
#pragma unroll
                for (int jj = TOPK - 1; jj > 0; jj--) {
                    if (arr[jj] < arr[jj - 1]) {
                        unsigned long long tmp = arr[jj]; arr[jj] = arr[jj - 1]; arr[jj - 1] = tmp;
                    }
                }
                guard = arr[TOPK - 1];
            }
        }
    }
    if (tid < 52) {
        int i = 2048 + tid;
        float4 v = r4[i];
        float vv[4] = {v.x, v.y, v.z, v.w};
#pragma unroll
        for (int j = 0; j < 4; j++) {
            unsigned long long k = ((unsigned long long)encf(vv[j]) << 32) | (unsigned)(4 * i + j);
            if (k < guard) {
                arr[TOPK - 1] = k;
#pragma unroll
                for (int jj = TOPK - 1; jj > 0; jj--) {
                    if (arr[jj] < arr[jj - 1]) {
                        unsigned long long tmp = arr[jj]; arr[jj] = arr[jj - 1]; arr[jj - 1] = tmp;
                    }
                }
                guard = arr[TOPK - 1];
            }
        }
    }

    // warp merge via head pointers (per-thread arr is sorted ascending)
    __shared__ unsigned long long warpTop[8 * TOPK];
    int head = 0;
    for (int r = 0; r < TOPK; r++) {
        unsigned long long v = (head < TOPK) ? arr[head] : ~0ull;
        unsigned long long m = v;
#pragma unroll
        for (int off = 16; off > 0; off >>= 1) {
            unsigned long long o = __shfl_xor_sync(0xffffffffu, m, off);
            m = (o < m) ? o : m;
        }
        unsigned ball = __ballot_sync(0xffffffffu, v == m);
        int w = __ffs(ball) - 1;
        if (lane == w) head++;
        if (lane == 0) warpTop[wid * TOPK + r] = m;
    }
    __syncthreads();

    if (wid == 0) {
        unsigned long long a3[3];
#pragma unroll
        for (int j = 0; j < 3; j++) {
            int idx = lane + j * 32;
            a3[j] = (idx < 8 * TOPK) ? warpTop[idx] : ~0ull;
        }
        if (a3[1] < a3[0]) { unsigned long long t = a3[0]; a3[0] = a3[1]; a3[1] = t; }
        if (a3[2] < a3[1]) { unsigned long long t = a3[1]; a3[1] = a3[2]; a3[2] = t; }
        if (a3[1] < a3[0]) { unsigned long long t = a3[0]; a3[0] = a3[1]; a3[1] = t; }
        int h = 0;
        for (int r = 0; r < TOPK; r++) {
            unsigned long long v = (h < 3) ? a3[h] : ~0ull;
            unsigned long long m = v;
#pragma unroll
            for (int off = 16; off > 0; off >>= 1) {
                unsigned long long o = __shfl_xor_sync(0xffffffffu, m, off);
                m = (o < m) ? o : m;
            }
            unsigned ball = __ballot_sync(0xffffffffu, v == m);
            int w = __ffs(ball) - 1;
            if (lane == w) h++;
            if (lane == 0) {
                g_topidx[bg * TOPK + r]  = (int)(m & 0xffffffffu);
                g_topcost[bg * TOPK + r] = decf((unsigned)(m >> 32));
            }
        }
    }
}

// ---------------- K4a: scatter counts + argmin keys ----------------
__global__ void k4a_scatter(const int* __restrict__ mask) {
    int t = blockIdx.x * blockDim.x + threadIdx.x;
    if (t >= BSZ * GG * TOPK) return;
    int bg = t / TOPK;
    int g  = bg % GG;
    int b  = bg / GG;
    if (mask[bg] == 0) return;
    int a = g_topidx[t];
    float c = g_topcost[t];
    atomicAdd(&g_cnt[b * AA + a], 1);
    unsigned long long k = ((unsigned long long)encf(c) << 32) | (unsigned)g;
    atomicMin(&g_pick[b * AA + a], k);
}

// ---------------- K4b: write final (sparse scatter) ----------------
__global__ void k4b_final(const int* __restrict__ mask, float* __restrict__ finalOut) {
    int t = blockIdx.x * blockDim.x + threadIdx.x;
    if (t >= BSZ * GG * TOPK) return;
    int bg = t / TOPK;
    int g  = bg % GG;
    int b  = bg / GG;
    if (mask[bg] == 0) return;
    int a = g_topidx[t];
    int c = g_cnt[b * AA + a];
    bool on;
    if (c > 1) {
        unsigned pg = (unsigned)(g_pick[b * AA + a] & 0xffffffffu);
        on = (pg == (unsigned)g);
    } else {
        on = true;
    }
    if (on) finalOut[(size_t)bg * AA + a] = 1.0f;
}

// ---------------- launch ----------------
extern "C" void kernel_launch(void* const* d_in, const int* in_sizes, int n_in,
                              void* d_out, int out_size) {
    const float* pboxes  = (const float*)d_in[0];
    const float* gboxes  = (const float*)d_in[1];
    const int*   maskgt  = (const int*)d_in[2];
    const float* scores  = (const float*)d_in[3];
    const int*   glabels = (const int*)d_in[4];

    const size_t N = (size_t)BSZ * GG * AA;
    float* finalOut = (float*)d_out;
    float* costOut  = finalOut + N;

    cudaMemsetAsync(d_out, 0, N * sizeof(float));
    k0_init<<<(BSZ * AA + 255) / 256, 256>>>();

    dim3 gridK1((AA + 31) / 32, BSZ);   // 263 x 32, 32 anchors per block
    k1_prep<<<gridK1, 256>>>(scores, pboxes);

    dim3 gridK2((AA + 255) / 256, BSZ);
    k2_cost<<<gridK2, 256>>>(pboxes, gboxes, glabels, costOut);

    k3_topk<<<BSZ * GG, 256>>>(costOut);

    int tot = BSZ * GG * TOPK;
    k4a_scatter<<<(tot + 255) / 256, 256>>>(maskgt);
    k4b_final<<<(tot + 255) / 256, 256>>>(maskgt, finalOut);
}

// round 13
// speedup vs baseline: 1.7594x; 1.7594x over previous
#include <cuda_runtime.h>
#include <math.h>

#define BSZ   32
#define AA    8400
#define GG    64
#define NCLS  80
#define TOPK  10
#define EPSV  1e-9f
#define BIGV  100000.0f

// ---------------- scratch (static device memory; no runtime alloc) ----------------
__device__ float              g_delta[(size_t)BSZ * NCLS * AA];  // [b, c, a] = log1p(-p) - log(p)
__device__ float              g_S[BSZ * AA];                     // S[b,a] = -sum_c log1p(-p)
__device__ float              g_atanP[BSZ * AA];                 // atan(w1/h1) (raw)
__device__ int                g_cnt[BSZ * AA];                   // pt_mask count per (b,a)
__device__ unsigned long long g_pick[BSZ * AA];                  // argmin key per (b,a)
__device__ int                g_topidx[BSZ * GG * TOPK];
__device__ float              g_topcost[BSZ * GG * TOPK];

// order-preserving float->uint map (monotone increasing)
__device__ __forceinline__ unsigned encf(float f) {
    unsigned u = __float_as_uint(f);
    unsigned mask = ((unsigned)((int)u >> 31)) | 0x80000000u;
    return u ^ mask;
}
__device__ __forceinline__ float decf(unsigned e) {
    unsigned u = (e & 0x80000000u) ? (e ^ 0x80000000u) : ~e;
    return __uint_as_float(u);
}

// ---------------- K0: init scratch ----------------
__global__ void k0_init() {
    int i = blockIdx.x * blockDim.x + threadIdx.x;
    if (i < BSZ * AA) { g_cnt[i] = 0; g_pick[i] = ~0ull; }
}

// ---------------- K1: prep with smem transpose (validated in R11) ----------------
__global__ void __launch_bounds__(256) k1_prep(const float* __restrict__ scores,
                                               const float* __restrict__ pboxes) {
    __shared__ float sm_l1[32][NCLS + 1];   // log1p(-p)
    __shared__ float sm_dl[32][NCLS + 1];   // log1p(-p) - log(p)

    int tid  = threadIdx.x;
    int lane = tid & 31, wid = tid >> 5;
    int b  = blockIdx.y;
    int a0 = blockIdx.x * 32;

    if (tid < 32) {
        int a = a0 + tid;
        if (a < AA) {
            float4 bx = reinterpret_cast<const float4*>(pboxes)[(size_t)b * AA + a];
            float w1 = __fsub_rn(bx.z, bx.x);
            float h1 = __fadd_rn(__fsub_rn(bx.w, bx.y), EPSV);
            g_atanP[b * AA + a] = atanf(__fdiv_rn(w1, h1));
        }
    }

    const float* sbase = scores + ((size_t)b * AA + a0) * NCLS;
    int maxE = (AA - a0 < 32 ? AA - a0 : 32) * NCLS;
#pragma unroll
    for (int e = tid; e < 32 * NCLS; e += 256) {
        if (e < maxE) {
            int ai = e / NCLS, c = e - ai * NCLS;
            float p  = fminf(fmaxf(sbase[e], 1e-7f), 0.99999994f);
            float lp = logf(p);
            float l1 = log1pf(-p);
            sm_l1[ai][c] = l1;
            sm_dl[ai][c] = __fsub_rn(l1, lp);
        }
    }
    __syncthreads();

#pragma unroll
    for (int q = 0; q < 4; q++) {
        int i = wid * 4 + q;
        int a = a0 + i;
        float acc = 0.0f;
        acc = __fadd_rn(acc, sm_l1[i][lane]);
        acc = __fadd_rn(acc, sm_l1[i][lane + 32]);
        if (lane + 64 < NCLS) acc = __fadd_rn(acc, sm_l1[i][lane + 64]);
#pragma unroll
        for (int off = 16; off > 0; off >>= 1)
            acc = __fadd_rn(acc, __shfl_down_sync(0xffffffffu, acc, off));
        if (lane == 0 && a < AA) g_S[b * AA + a] = -acc;
    }

    int a = a0 + lane;
    if (a < AA) {
#pragma unroll
        for (int c = wid; c < NCLS; c += 8)
            g_delta[((size_t)b * NCLS + c) * AA + a] = sm_dl[lane][c];
    }
}

// ---------------- K2: cost matrix (bit-faithful f32 emulation, validated) ----------------
__global__ void k2_cost(const float* __restrict__ pboxes, const float* __restrict__ gboxes,
                        const int* __restrict__ glabels, float* __restrict__ costOut) {
    __shared__ float sgx1[GG], sgy1[GG], sgx2[GG], sgy2[GG];
    __shared__ float sglx[GG], sgly[GG], sghx[GG], sghy[GG];
    __shared__ float sgsx[GG], sgsy[GG], swh[GG], sat[GG];
    __shared__ int   slab[GG];

    int b   = blockIdx.y;
    int tid = threadIdx.x;
    if (tid < GG) {
        float4 gb = reinterpret_cast<const float4*>(gboxes)[b * GG + tid];
        sgx1[tid] = gb.x; sgy1[tid] = gb.y; sgx2[tid] = gb.z; sgy2[tid] = gb.w;
        float gcx = __fmul_rn(__fadd_rn(gb.x, gb.z), 0.5f);
        float gcy = __fmul_rn(__fadd_rn(gb.y, gb.w), 0.5f);
        sglx[tid] = __fsub_rn(gcx, 2.5f); sghx[tid] = __fadd_rn(gcx, 2.5f);
        sgly[tid] = __fsub_rn(gcy, 2.5f); sghy[tid] = __fadd_rn(gcy, 2.5f);
        sgsx[tid] = __fadd_rn(gb.x, gb.z); sgsy[tid] = __fadd_rn(gb.y, gb.w);
        float w2 = __fsub_rn(gb.z, gb.x);
        float h2 = __fadd_rn(__fsub_rn(gb.w, gb.y), EPSV);
        swh[tid] = __fmul_rn(w2, h2);
        sat[tid] = atanf(__fdiv_rn(w2, h2));
        slab[tid] = glabels[b * GG + tid];
    }
    __syncthreads();

    int a = blockIdx.x * blockDim.x + tid;
    if (a >= AA) return;

    float4 pb = reinterpret_cast<const float4*>(pboxes)[(size_t)b * AA + a];
    float px1 = pb.x, py1 = pb.y, px2 = pb.z, py2 = pb.w;
    float w1   = __fsub_rn(px2, px1);
    float h1   = __fadd_rn(__fsub_rn(py2, py1), EPSV);
    float w1h1 = __fmul_rn(w1, h1);
    float pcx  = __fmul_rn(__fadd_rn(px1, px2), 0.5f);
    float pcy  = __fmul_rn(__fadd_rn(py1, py2), 0.5f);
    float atP  = g_atanP[b * AA + a];
    float Sv   = g_S[b * AA + a];
    const float* dbase = g_delta + (size_t)b * NCLS * AA + a;
    float* outp = costOut + (size_t)b * GG * AA + a;

#pragma unroll 8
    for (int g = 0; g < GG; g++) {
        float gx1 = sgx1[g], gy1 = sgy1[g], gx2 = sgx2[g], gy2 = sgy2[g];
        float iw    = fmaxf(__fsub_rn(fminf(px2, gx2), fmaxf(px1, gx1)), 0.0f);
        float ih    = fmaxf(__fsub_rn(fminf(py2, gy2), fmaxf(py1, gy1)), 0.0f);
        float inter = __fmul_rn(iw, ih);
        float uni   = __fadd_rn(__fsub_rn(__fadd_rn(w1h1, swh[g]), inter), EPSV);
        float iou   = __fdiv_rn(inter, uni);
        float cw = __fsub_rn(fmaxf(px2, gx2), fminf(px1, gx1));
        float ch = __fsub_rn(fmaxf(py2, gy2), fminf(py1, gy1));
        float c2 = __fadd_rn(__fadd_rn(__fmul_rn(cw, cw), __fmul_rn(ch, ch)), EPSV);
        float dx = __fsub_rn(__fsub_rn(sgsx[g], px1), px2);
        float dy = __fsub_rn(__fsub_rn(sgsy[g], py1), py2);
        float d2 = __fmul_rn(__fadd_rn(__fmul_rn(dx, dx), __fmul_rn(dy, dy)), 0.25f);
        float t = __fsub_rn(sat[g], atP);
        float v = __fmul_rn(0.4052847345693511f, __fmul_rn(t, t));
        float alpha = __fdiv_rn(v, __fadd_rn(__fsub_rn(v, iou), 1.0f));
        float ciou  = __fsub_rn(iou, __fadd_rn(__fdiv_rn(d2, c2), __fmul_rn(v, alpha)));
        float dl  = __ldg(dbase + (size_t)slab[g] * AA);
        float cls = __fadd_rn(Sv, dl);
        bool both = (pcx > gx1) & (pcy > gy1) & (gx2 > pcx) & (gy2 > pcy) &
                    (pcx > sglx[g]) & (pcy > sgly[g]) & (sghx[g] > pcx) & (sghy[g] > pcy);
        float cost = __fadd_rn(__fadd_rn(cls, __fmul_rn(3.0f, ciou)), both ? 0.0f : BIGV);
        outp[(size_t)g * AA] = cost;
    }
}

// ---------------- K3: warp-collective distributed top-10 ----------------
// Lanes 0..9 of each warp hold the warp's 10 smallest (enc(cost)<<32 | idx) keys,
// sorted ascending by lane. Stream path: min4 + one ballot per 128-element chunk.
// Inserts are warp-uniform (no divergence, no spills). Within-warp stream index is
// strictly ascending, so the strict guard comparison preserves lowest-index ties.
__global__ void __launch_bounds__(256) k3_topk(const float* __restrict__ costOut) {
    int bg = blockIdx.x;  // b*GG + g
    const float4* r4 = reinterpret_cast<const float4*>(costOut + (size_t)bg * AA);
    int tid = threadIdx.x;
    int lane = tid & 31, wid = tid >> 5;

    const unsigned long long SENT = 0xFF800000FFFFFFFFull;  // enc(+inf) | idx max
    unsigned long long val = SENT;                          // lane r<10: r-th smallest
    float guard_f = __int_as_float(0x7F800000);             // +inf

    // 8400 floats = 2100 float4; 2100 = 8*256 + 52
    for (int it = 0; it < 9; it++) {
        int i = tid + it * 256;
        float4 v = make_float4(0.f, 0.f, 0.f, 0.f);
        bool has = false;
        if (i < 2100) {
            v = r4[i];
            float m = fminf(fminf(v.x, v.y), fminf(v.z, v.w));
            has = (m < guard_f);
        }
        unsigned mask = __ballot_sync(0xffffffffu, has);
        while (mask) {
            int leader = __ffs(mask) - 1;
            mask &= mask - 1;
            float b0 = __shfl_sync(0xffffffffu, v.x, leader);
            float b1 = __shfl_sync(0xffffffffu, v.y, leader);
            float b2 = __shfl_sync(0xffffffffu, v.z, leader);
            float b3 = __shfl_sync(0xffffffffu, v.w, leader);
            int bi = __shfl_sync(0xffffffffu, i, leader) * 4;
            float cc[4] = {b0, b1, b2, b3};
#pragma unroll
            for (int j = 0; j < 4; j++) {
                float c = cc[j];
                if (c < guard_f) {   // warp-uniform (broadcast values)
                    unsigned long long key =
                        ((unsigned long long)encf(c) << 32) | (unsigned)(bi + j);
                    unsigned bal = __ballot_sync(0xffffffffu, val < key) & 0x3FFu;
                    int rank = __popc(bal);          // insertion position 0..9
                    unsigned long long up = __shfl_up_sync(0xffffffffu, val, 1);
                    if (lane < 10) {
                        if (lane == rank)      val = key;
                        else if (lane > rank)  val = up;
                    }
                    unsigned long long gk = __shfl_sync(0xffffffffu, val, 9);
                    guard_f = decf((unsigned)(gk >> 32));
                }
            }
        }
    }

    // Each warp deposits its sorted 10; warp 0 merges 8 sorted lists via head pointers.
    __shared__ unsigned long long sm[8 * TOPK];
    if (lane < TOPK) sm[wid * TOPK + lane] = val;
    __syncthreads();

    if (wid == 0) {
        int head = 0;
        for (int r = 0; r < TOPK; r++) {
            unsigned long long v2 = (lane < 8 && head < TOPK) ? sm[lane * TOPK + head] : ~0ull;
            unsigned long long m = v2;
#pragma unroll
            for (int off = 16; off > 0; off >>= 1) {
                unsigned long long o = __shfl_xor_sync(0xffffffffu, m, off);
                m = (o < m) ? o : m;
            }
            unsigned ball = __ballot_sync(0xffffffffu, v2 == m);
            int w = __ffs(ball) - 1;
            if (lane == w) head++;
            if (lane == 0) {
                g_topidx[bg * TOPK + r]  = (int)(m & 0xffffffffu);
                g_topcost[bg * TOPK + r] = decf((unsigned)(m >> 32));
            }
        }
    }
}

// ---------------- K4a: scatter counts + argmin keys ----------------
__global__ void k4a_scatter(const int* __restrict__ mask) {
    int t = blockIdx.x * blockDim.x + threadIdx.x;
    if (t >= BSZ * GG * TOPK) return;
    int bg = t / TOPK;
    int g  = bg % GG;
    int b  = bg / GG;
    if (mask[bg] == 0) return;
    int a = g_topidx[t];
    float c = g_topcost[t];
    atomicAdd(&g_cnt[b * AA + a], 1);
    unsigned long long k = ((unsigned long long)encf(c) << 32) | (unsigned)g;
    atomicMin(&g_pick[b * AA + a], k);
}

// ---------------- K4b: write final (sparse scatter) ----------------
__global__ void k4b_final(const int* __restrict__ mask, float* __restrict__ finalOut) {
    int t = blockIdx.x * blockDim.x + threadIdx.x;
    if (t >= BSZ * GG * TOPK) return;
    int bg = t / TOPK;
    int g  = bg % GG;
    int b  = bg / GG;
    if (mask[bg] == 0) return;
    int a = g_topidx[t];
    int c = g_cnt[b * AA + a];
    bool on;
    if (c > 1) {
        unsigned pg = (unsigned)(g_pick[b * AA + a] & 0xffffffffu);
        on = (pg == (unsigned)g);
    } else {
        on = true;
    }
    if (on) finalOut[(size_t)bg * AA + a] = 1.0f;
}

// ---------------- launch ----------------
extern "C" void kernel_launch(void* const* d_in, const int* in_sizes, int n_in,
                              void* d_out, int out_size) {
    const float* pboxes  = (const float*)d_in[0];
    const float* gboxes  = (const float*)d_in[1];
    const int*   maskgt  = (const int*)d_in[2];
    const float* scores  = (const float*)d_in[3];
    const int*   glabels = (const int*)d_in[4];

    const size_t N = (size_t)BSZ * GG * AA;
    float* finalOut = (float*)d_out;
    float* costOut  = finalOut + N;

    cudaMemsetAsync(d_out, 0, N * sizeof(float));
    k0_init<<<(BSZ * AA + 255) / 256, 256>>>();

    dim3 gridK1((AA + 31) / 32, BSZ);   // 263 x 32, 32 anchors per block
    k1_prep<<<gridK1, 256>>>(scores, pboxes);

    dim3 gridK2((AA + 255) / 256, BSZ);
    k2_cost<<<gridK2, 256>>>(pboxes, gboxes, glabels, costOut);

    k3_topk<<<BSZ * GG, 256>>>(costOut);

    int tot = BSZ * GG * TOPK;
    k4a_scatter<<<(tot + 255) / 256, 256>>>(maskgt);
    k4b_final<<<(tot + 255) / 256, 256>>>(maskgt, finalOut);
}